// round 16
// baseline (speedup 1.0000x reference)
#include <cuda_runtime.h>
#include <math.h>
#include <stdint.h>

#define Bsz 256
#define Ssz 2048
#define Dsz 64
#define Hsz 256
#define NCTA 128          // persistent CTAs, 1/SM, all co-resident
#define NTHR 512          // 16 warps; warp w owns k-slice [16w,16w+16) and row w
#define WPAD 260          // state row stride (floats)

// ---------------- device scratch ----------------
__device__ float g_pre0p[(size_t)NCTA * Ssz * 512];  // private pre0 [cta][s][row16][lane32]
__device__ float g_h0[2][Bsz * Hsz];                 // layer-0 state, double buffered
__device__ float g_h1[2][Bsz * Hsz];                 // layer-1 state, double buffered
__device__ unsigned int g_flags[NCTA];               // barrier flags (zeroed by init)

__device__ __forceinline__ float tanh_fast(float x) {
    float y; asm("tanh.approx.f32 %0, %1;" : "=f"(y) : "f"(x)); return y;
}
__device__ __forceinline__ unsigned long long fma2(unsigned long long a,
                                                   unsigned long long b,
                                                   unsigned long long c) {
    unsigned long long d;
    asm("fma.rn.f32x2 %0, %1, %2, %3;" : "=l"(d) : "l"(a), "l"(b), "l"(c));
    return d;
}
__device__ __forceinline__ unsigned long long add2(unsigned long long a,
                                                   unsigned long long b) {
    unsigned long long d;
    asm("add.rn.f32x2 %0, %1, %2;" : "=l"(d) : "l"(a), "l"(b));
    return d;
}
__device__ __forceinline__ float hsum2(unsigned long long a) {
    float2 f = *reinterpret_cast<float2*>(&a);
    return f.x + f.y;
}
__device__ __forceinline__ void st_release(unsigned int* p, unsigned int v) {
    asm volatile("st.release.gpu.global.u32 [%0], %1;" :: "l"(p), "r"(v) : "memory");
}
__device__ __forceinline__ unsigned int ld_acquire(const unsigned int* p) {
    unsigned int v;
    asm volatile("ld.acquire.gpu.global.u32 %0, [%1];" : "=r"(v) : "l"(p) : "memory");
    return v;
}

// ---------------- init: zero flags + seed states ----------------
__global__ void init_kernel() {
    const int idx = blockIdx.x * blockDim.x + threadIdx.x;
    if (idx < NCTA) g_flags[idx] = 0u;
    if (idx < Bsz * Hsz) {
        g_h1[0][idx] = 0.0f;
        g_h1[1][idx] = 0.0f;
    }
}

__global__ void __launch_bounds__(NTHR, 1)
fused_kernel(const float* __restrict__ x,
             const float* __restrict__ Wih0,
             const float* __restrict__ Whh0,
             const float* __restrict__ bih0,
             const float* __restrict__ bhh0,
             const float* __restrict__ Wih1,
             const float* __restrict__ Whh1,
             const float* __restrict__ bih1,
             const float* __restrict__ bhh1,
             const float* __restrict__ Wout,
             const float* __restrict__ bout,
             float* __restrict__ out) {
    extern __shared__ float smem[];
    float* sH0   = smem;                     // [16][WPAD]  h0_{i-1}
    float* sH1   = sH0 + 16 * WPAD;          // [16][WPAD]  h1_{i-2}
    float* sRedA = sH1 + 16 * WPAD;          // 16 tiles [16][33]: Whh0 partials
    float* sRedB = sRedA + 16 * 528;         // 16 tiles [16][33]: Wih1 partials
    float* sRedC = sRedB + 16 * 528;         // 16 tiles [16][33]: Whh1 partials
    float* sWH   = sRedC + 16 * 528;         // [128 k2][32 col] u64  Whh1 weights

    const int tid  = threadIdx.x;
    const int cta  = blockIdx.x;
    const int grp8 = (cta >> 3) * 8;
    const int b0   = (cta >> 3) * 16;         // 16 batch rows
    const int h0c  = (cta & 7) * 32;          // 32 h columns
    const int lane = tid & 31;
    const int warp = tid >> 5;                // 0..15: k-slice AND finalize row

    const int srow = warp, sc = lane;         // staging: warp w stages row w

    // ================= phase 1: pre0_priv = x @ Wih0^T + (b_ih0+b_hh0) =================
    {
        float* sW = sH0;   // scratch, re-zeroed later
        for (int it = tid; it < 32 * 16; it += NTHR) {
            const int col = it >> 4, kq = it & 15;
            *(float4*)(sW + (kq * 32 + col) * 4) =
                *(const float4*)(Wih0 + (size_t)(h0c + col) * Dsz + kq * 4);
        }
        __syncthreads();
        const float bsum = bih0[h0c + lane] + bhh0[h0c + lane];

        for (int s = warp; s < Ssz; s += 16) {
            float* dst = g_pre0p + ((size_t)cta * Ssz + s) * 512;
#pragma unroll 2
            for (int r = 0; r < 16; ++r) {
                const float4* xr = (const float4*)(x + ((size_t)(b0 + r) * Ssz + s) * Dsz);
                float a = 0.0f;
#pragma unroll
                for (int c2 = 0; c2 < 2; ++c2) {
                    float4 xv[8];
#pragma unroll
                    for (int q = 0; q < 8; ++q) xv[q] = __ldg(xr + c2 * 8 + q);
#pragma unroll
                    for (int q = 0; q < 8; ++q) {
                        float4 w = *(const float4*)(sW + ((c2 * 8 + q) * 32 + lane) * 4);
                        a += w.x * xv[q].x + w.y * xv[q].y + w.z * xv[q].z + w.w * xv[q].w;
                    }
                }
                dst[r * 32 + lane] = a + bsum;
            }
        }
    }

    // ---- persistent register weights (Whh0, Wih1); Whh1 goes to SMEM ----
    unsigned long long wA[8], wI[8];
    {
        const size_t off = (size_t)(h0c + lane) * Hsz + warp * 16;
#pragma unroll
        for (int j = 0; j < 4; ++j) {
            ulonglong2 a = *(const ulonglong2*)(Whh0 + off + j * 4);
            ulonglong2 b = *(const ulonglong2*)(Wih1 + off + j * 4);
            wA[j * 2] = a.x; wA[j * 2 + 1] = a.y;
            wI[j * 2] = b.x; wI[j * 2 + 1] = b.y;
        }
    }
    const float bias1 = bih1[h0c + lane] + bhh1[h0c + lane];

    __syncthreads();   // pre0's sW use done
    // ---- Whh1 -> sWH as u64 pairs: slot[k2][col] ----
    {
        unsigned long long* wh64 = (unsigned long long*)sWH;
        const size_t off = (size_t)(h0c + lane) * Hsz + warp * 16;
#pragma unroll
        for (int j = 0; j < 4; ++j) {
            ulonglong2 c = *(const ulonglong2*)(Whh1 + off + j * 4);
            wh64[(warp * 8 + 2 * j + 0) * 32 + lane] = c.x;
            wh64[(warp * 8 + 2 * j + 1) * 32 + lane] = c.y;
        }
    }
    // ---- zero sH0 (= h0_{-1}); publish readiness (flag = 1) ----
    for (int it = tid; it < 16 * WPAD; it += NTHR) sH0[it] = 0.0f;
    __syncthreads();
    if (tid == 0) st_release(&g_flags[cta], 1u);

    // all-thread acquire poll: orders each thread's subsequent loads (no sync needed)
#define POLL_ALL(VAL) do {                                                 \
        const unsigned int tgt = (VAL);                                    \
        while (ld_acquire(&g_flags[grp8 + (tid & 7)]) < tgt) { }           \
    } while (0)

    float p = g_pre0p[(size_t)cta * Ssz * 512 + warp * 32 + lane];   // pre0 for i=0

    // ================= phase 2: pipelined two-layer recurrence =================
    for (int i = 0; i <= Ssz; ++i) {
        const bool doA = (i < Ssz);    // h0_i work exists
        const bool doC = (i >= 1);     // h1_{i-1} work exists

        // ---- P1: poll h1_{i-2}; issue its staging LDGs; merged wA+wI pass over sH0 ----
        POLL_ALL(2u * i + 1u);
        float4 e0, e1;
        {
            const float* src = g_h1[i & 1] + (size_t)(b0 + srow) * Hsz;  // (i-2)&1 == i&1
            e0 = __ldcg((const float4*)(src + sc * 4));
            e1 = __ldcg((const float4*)(src + (sc + 32) * 4));
        }
        {
            float* redA_ = sRedA + warp * 528;
            float* redB_ = sRedB + warp * 528;
            const float* S = sH0 + warp * 16;
            ulonglong2 c0 = ((const ulonglong2*)S)[0];
            ulonglong2 c1 = ((const ulonglong2*)S)[1];
            ulonglong2 c2 = ((const ulonglong2*)S)[2];
            ulonglong2 c3 = ((const ulonglong2*)S)[3];
#pragma unroll
            for (int r = 0; r < 16; ++r) {
                ulonglong2 n0 = c0, n1 = c1, n2 = c2, n3 = c3;
                if (r < 15) {
                    const ulonglong2* Sn = (const ulonglong2*)(S + (r + 1) * WPAD);
                    n0 = Sn[0]; n1 = Sn[1]; n2 = Sn[2]; n3 = Sn[3];
                }
                if (doA) {
                    unsigned long long a0 = fma2(wA[0], c0.x, 0ull);
                    unsigned long long a1 = fma2(wA[1], c0.y, 0ull);
                    unsigned long long a2 = fma2(wA[2], c1.x, 0ull);
                    unsigned long long a3 = fma2(wA[3], c1.y, 0ull);
                    a0 = fma2(wA[4], c2.x, a0);
                    a1 = fma2(wA[5], c2.y, a1);
                    a2 = fma2(wA[6], c3.x, a2);
                    a3 = fma2(wA[7], c3.y, a3);
                    redA_[r * 33 + lane] = hsum2(add2(add2(a0, a1), add2(a2, a3)));
                }
                if (doC) {
                    unsigned long long a0 = fma2(wI[0], c0.x, 0ull);
                    unsigned long long a1 = fma2(wI[1], c0.y, 0ull);
                    unsigned long long a2 = fma2(wI[2], c1.x, 0ull);
                    unsigned long long a3 = fma2(wI[3], c1.y, 0ull);
                    a0 = fma2(wI[4], c2.x, a0);
                    a1 = fma2(wI[5], c2.y, a1);
                    a2 = fma2(wI[6], c3.x, a2);
                    a3 = fma2(wI[7], c3.y, a3);
                    redB_[r * 33 + lane] = hsum2(add2(add2(a0, a1), add2(a2, a3)));
                }
                c0 = n0; c1 = n1; c2 = n2; c3 = n3;
            }
        }
        {   // store staged h1_{i-2}
            float* dst = sH1 + srow * WPAD;
            *(float4*)(dst + sc * 4)        = e0;
            *(float4*)(dst + (sc + 32) * 4) = e1;
        }
        __syncthreads();     // S1

        // ---- P2: finalize h0_i (overlaps with) C2: Whh1 pass over sH1 ----
        if (doA) {           // tree reduce redA
            float t[16];
#pragma unroll
            for (int q = 0; q < 16; ++q) t[q] = sRedA[q * 528 + warp * 33 + lane];
#pragma unroll
            for (int st = 1; st < 16; st <<= 1)
#pragma unroll
                for (int j = 0; j < 16; j += 2 * st) t[j] += t[j + st];
            __stcg(&g_h0[i & 1][(size_t)(b0 + warp) * Hsz + h0c + lane],
                   tanh_fast(p + t[0]));
        }
        if (doC) {
            unsigned long long wH[8];
            const unsigned long long* wh64 = (const unsigned long long*)sWH;
#pragma unroll
            for (int j = 0; j < 8; ++j) wH[j] = wh64[(warp * 8 + j) * 32 + lane];
            float* red = sRedC + warp * 528;
            const float* S = sH1 + warp * 16;
            ulonglong2 c0 = ((const ulonglong2*)S)[0];
            ulonglong2 c1 = ((const ulonglong2*)S)[1];
            ulonglong2 c2 = ((const ulonglong2*)S)[2];
            ulonglong2 c3 = ((const ulonglong2*)S)[3];
#pragma unroll
            for (int r = 0; r < 16; ++r) {
                ulonglong2 n0 = c0, n1 = c1, n2 = c2, n3 = c3;
                if (r < 15) {
                    const ulonglong2* Sn = (const ulonglong2*)(S + (r + 1) * WPAD);
                    n0 = Sn[0]; n1 = Sn[1]; n2 = Sn[2]; n3 = Sn[3];
                }
                unsigned long long a0 = fma2(wH[0], c0.x, 0ull);
                unsigned long long a1 = fma2(wH[1], c0.y, 0ull);
                unsigned long long a2 = fma2(wH[2], c1.x, 0ull);
                unsigned long long a3 = fma2(wH[3], c1.y, 0ull);
                a0 = fma2(wH[4], c2.x, a0);
                a1 = fma2(wH[5], c2.y, a1);
                a2 = fma2(wH[6], c3.x, a2);
                a3 = fma2(wH[7], c3.y, a3);
                red[r * 33 + lane] = hsum2(add2(add2(a0, a1), add2(a2, a3)));
                c0 = n0; c1 = n1; c2 = n2; c3 = n3;
            }
        }
        __syncthreads();     // S2
        if (tid == 0) st_release(&g_flags[cta], 2u * i + 2u);   // publish h0_i

        // ---- P3: poll peers' h0_i; stage it (LDGs fly under h1 finalize) ----
        POLL_ALL(2u * i + 2u);
        if (doA) {
            const float* src = g_h0[i & 1] + (size_t)(b0 + srow) * Hsz;
            e0 = __ldcg((const float4*)(src + sc * 4));
            e1 = __ldcg((const float4*)(src + (sc + 32) * 4));
        }
        if (doC) {           // tree reduce redB + redC
            float t[16], u[16];
#pragma unroll
            for (int q = 0; q < 16; ++q) t[q] = sRedB[q * 528 + warp * 33 + lane];
#pragma unroll
            for (int q = 0; q < 16; ++q) u[q] = sRedC[q * 528 + warp * 33 + lane];
#pragma unroll
            for (int st = 1; st < 16; st <<= 1)
#pragma unroll
                for (int j = 0; j < 16; j += 2 * st) { t[j] += t[j + st]; u[j] += u[j + st]; }
            __stcg(&g_h1[(i - 1) & 1][(size_t)(b0 + warp) * Hsz + h0c + lane],
                   tanh_fast(bias1 + t[0] + u[0]));
        }
        if (doA) {
            float* dst = sH0 + srow * WPAD;
            *(float4*)(dst + sc * 4)        = e0;
            *(float4*)(dst + (sc + 32) * 4) = e1;
            if (i + 1 < Ssz)
                p = g_pre0p[((size_t)cta * Ssz + i + 1) * 512 + warp * 32 + lane];
        }
        __syncthreads();     // S3
        if (tid == 0) st_release(&g_flags[cta], 2u * i + 3u);   // publish h1_{i-1}
    }

    // ================= phase 3: head (16 CTAs, one per batch group) =================
    if ((cta & 7) == 0) {
        POLL_ALL(2u * Ssz + 3u);
        __syncthreads();
        if (warp < 8) {
            const float bo = bout[0];
#pragma unroll
            for (int rr = 0; rr < 2; ++rr) {
                const int b = b0 + warp * 2 + rr;
                const float* h = g_h1[(Ssz - 1) & 1] + (size_t)b * Hsz;
                float s = 0.0f;
#pragma unroll
                for (int j = 0; j < 8; ++j)
                    s += __ldcg(&h[lane + 32 * j]) * Wout[lane + 32 * j];
#pragma unroll
                for (int o = 16; o > 0; o >>= 1) s += __shfl_down_sync(0xFFFFFFFFu, s, o);
                if (lane == 0) out[b] = 1.0f / (1.0f + expf(-(s + bo)));
            }
        }
    }
#undef POLL_ALL
}

// ---------------- launch ----------------
extern "C" void kernel_launch(void* const* d_in, const int* in_sizes, int n_in,
                              void* d_out, int out_size) {
    const float* x    = (const float*)d_in[0];
    const float* Wih0 = (const float*)d_in[1];
    const float* Whh0 = (const float*)d_in[2];
    const float* bih0 = (const float*)d_in[3];
    const float* bhh0 = (const float*)d_in[4];
    const float* Wih1 = (const float*)d_in[5];
    const float* Whh1 = (const float*)d_in[6];
    const float* bih1 = (const float*)d_in[7];
    const float* bhh1 = (const float*)d_in[8];
    const float* Wout = (const float*)d_in[9];
    const float* bout = (const float*)d_in[10];
    float* out = (float*)d_out;

    // smem: 2*16*WPAD + 48*528 + 256*32 floats = 8320 + 25344 + 8192 = 41856 f = 167,424 B
    const int smem_bytes = (2 * 16 * WPAD + 48 * 528 + 256 * 32) * (int)sizeof(float);
    static int configured = 0;
    if (!configured) {
        cudaFuncSetAttribute(fused_kernel, cudaFuncAttributeMaxDynamicSharedMemorySize, smem_bytes);
        configured = 1;
    }

    init_kernel<<<(Bsz * Hsz + 511) / 512, 512>>>();
    fused_kernel<<<NCTA, NTHR, smem_bytes>>>(x, Wih0, Whh0, bih0, bhh0,
                                             Wih1, Whh1, bih1, bhh1,
                                             Wout, bout, out);
}

// round 17
// speedup vs baseline: 4.2835x; 4.2835x over previous
#include <cuda_runtime.h>
#include <math.h>
#include <stdint.h>

#define Bsz 256
#define Ssz 2048
#define Dsz 64
#define Hsz 256
#define NCTA 128          // persistent CTAs, 1/SM, all co-resident
#define NTHR 512          // 16 warps; warp w owns k-slice [16w,16w+16) and row w
#define WPAD 260          // state row stride (floats)

// ---------------- device scratch ----------------
__device__ float g_pre0p[(size_t)NCTA * Ssz * 512];  // private pre0 [cta][s][row16][lane32]
__device__ float g_h0[2][Bsz * Hsz];                 // layer-0 state, double buffered
__device__ float g_h1[2][Bsz * Hsz];                 // layer-1 state, double buffered
__device__ unsigned int g_flags[NCTA];               // barrier flags (zeroed by init)

__device__ __forceinline__ float tanh_fast(float x) {
    float y; asm("tanh.approx.f32 %0, %1;" : "=f"(y) : "f"(x)); return y;
}
__device__ __forceinline__ unsigned long long fma2(unsigned long long a,
                                                   unsigned long long b,
                                                   unsigned long long c) {
    unsigned long long d;
    asm("fma.rn.f32x2 %0, %1, %2, %3;" : "=l"(d) : "l"(a), "l"(b), "l"(c));
    return d;
}
__device__ __forceinline__ unsigned long long add2(unsigned long long a,
                                                   unsigned long long b) {
    unsigned long long d;
    asm("add.rn.f32x2 %0, %1, %2;" : "=l"(d) : "l"(a), "l"(b));
    return d;
}
__device__ __forceinline__ float hsum2(unsigned long long a) {
    float2 f = *reinterpret_cast<float2*>(&a);
    return f.x + f.y;
}
__device__ __forceinline__ void st_release(unsigned int* p, unsigned int v) {
    asm volatile("st.release.gpu.global.u32 [%0], %1;" :: "l"(p), "r"(v) : "memory");
}
__device__ __forceinline__ unsigned int ld_acquire(const unsigned int* p) {
    unsigned int v;
    asm volatile("ld.acquire.gpu.global.u32 %0, [%1];" : "=r"(v) : "l"(p) : "memory");
    return v;
}

// ---------------- init: zero flags + seed states ----------------
__global__ void init_kernel() {
    const int idx = blockIdx.x * blockDim.x + threadIdx.x;
    if (idx < NCTA) g_flags[idx] = 0u;
    if (idx < Bsz * Hsz) {
        g_h1[0][idx] = 0.0f;
        g_h1[1][idx] = 0.0f;
    }
}

__global__ void __launch_bounds__(NTHR, 1)
fused_kernel(const float* __restrict__ x,
             const float* __restrict__ Wih0,
             const float* __restrict__ Whh0,
             const float* __restrict__ bih0,
             const float* __restrict__ bhh0,
             const float* __restrict__ Wih1,
             const float* __restrict__ Whh1,
             const float* __restrict__ bih1,
             const float* __restrict__ bhh1,
             const float* __restrict__ Wout,
             const float* __restrict__ bout,
             float* __restrict__ out) {
    extern __shared__ float smem[];
    float* sH0   = smem;                     // [16][WPAD]  h0_{i-1}
    float* sH1   = sH0 + 16 * WPAD;          // [16][WPAD]  h1_{i-2}
    float* sRedA = sH1 + 16 * WPAD;          // 16 tiles [16][33]: Whh0 partials, then Whh1
    float* sRedB = sRedA + 16 * 528;         // 16 tiles [16][33]: Wih1 partials
    float* sWH   = sRedB + 16 * 528;         // [128 k2][32 col] u64  Whh1 weights

    const int tid  = threadIdx.x;
    const int cta  = blockIdx.x;
    const int grp8 = (cta >> 3) * 8;
    const int b0   = (cta >> 3) * 16;         // 16 batch rows
    const int h0c  = (cta & 7) * 32;          // 32 h columns
    const int lane = tid & 31;
    const int warp = tid >> 5;                // 0..15: k-slice AND finalize row

    const int srow = warp, sc = lane;         // staging: warp w stages row w

    // ================= phase 1: pre0_priv = x @ Wih0^T + (b_ih0+b_hh0) =================
    {
        float* sW = sH0;   // scratch, re-zeroed later
        for (int it = tid; it < 32 * 16; it += NTHR) {
            const int col = it >> 4, kq = it & 15;
            *(float4*)(sW + (kq * 32 + col) * 4) =
                *(const float4*)(Wih0 + (size_t)(h0c + col) * Dsz + kq * 4);
        }
        __syncthreads();
        const float bsum = bih0[h0c + lane] + bhh0[h0c + lane];

        for (int s = warp; s < Ssz; s += 16) {
            float* dst = g_pre0p + ((size_t)cta * Ssz + s) * 512;
#pragma unroll 2
            for (int r = 0; r < 16; ++r) {
                const float4* xr = (const float4*)(x + ((size_t)(b0 + r) * Ssz + s) * Dsz);
                float a = 0.0f;
#pragma unroll
                for (int c2 = 0; c2 < 2; ++c2) {
                    float4 xv[8];
#pragma unroll
                    for (int q = 0; q < 8; ++q) xv[q] = __ldg(xr + c2 * 8 + q);
#pragma unroll
                    for (int q = 0; q < 8; ++q) {
                        float4 w = *(const float4*)(sW + ((c2 * 8 + q) * 32 + lane) * 4);
                        a += w.x * xv[q].x + w.y * xv[q].y + w.z * xv[q].z + w.w * xv[q].w;
                    }
                }
                dst[r * 32 + lane] = a + bsum;
            }
        }
    }

    // ---- persistent register weights (Whh0, Wih1); Whh1 goes to SMEM ----
    unsigned long long wA[8], wI[8];
    {
        const size_t off = (size_t)(h0c + lane) * Hsz + warp * 16;
#pragma unroll
        for (int j = 0; j < 4; ++j) {
            ulonglong2 a = *(const ulonglong2*)(Whh0 + off + j * 4);
            ulonglong2 b = *(const ulonglong2*)(Wih1 + off + j * 4);
            wA[j * 2] = a.x; wA[j * 2 + 1] = a.y;
            wI[j * 2] = b.x; wI[j * 2 + 1] = b.y;
        }
    }
    const float bias1 = bih1[h0c + lane] + bhh1[h0c + lane];

    __syncthreads();   // pre0's sW use done
    // ---- Whh1 -> sWH as u64 pairs: slot[k2][col] ----
    {
        unsigned long long* wh64 = (unsigned long long*)sWH;
        const size_t off = (size_t)(h0c + lane) * Hsz + warp * 16;
#pragma unroll
        for (int j = 0; j < 4; ++j) {
            ulonglong2 c = *(const ulonglong2*)(Whh1 + off + j * 4);
            wh64[(warp * 8 + 2 * j + 0) * 32 + lane] = c.x;
            wh64[(warp * 8 + 2 * j + 1) * 32 + lane] = c.y;
        }
    }
    // ---- zero sH0 (= h0_{-1}); publish readiness (flag = 1) ----
    for (int it = tid; it < 16 * WPAD; it += NTHR) sH0[it] = 0.0f;
    __syncthreads();
    if (tid == 0) st_release(&g_flags[cta], 1u);

#define POLL(VAL) do {                                                     \
        if (tid < 8) {                                                     \
            const unsigned int tgt = (VAL);                                \
            while (ld_acquire(&g_flags[grp8 + tid]) < tgt) { }             \
        }                                                                  \
    } while (0)

    float p = g_pre0p[(size_t)cta * Ssz * 512 + warp * 32 + lane];   // pre0 for i=0

    // ================= phase 2: pipelined two-layer recurrence =================
    for (int i = 0; i <= Ssz; ++i) {
        const bool doA = (i < Ssz);    // h0_i work exists
        const bool doC = (i >= 1);     // h1_{i-1} work exists

        // ---- A (merged): Whh0 AND Wih1 partials, one pass over sH0, row-prefetched ----
        {
            float* redA_ = sRedA + warp * 528;
            float* redB_ = sRedB + warp * 528;
            const float* S = sH0 + warp * 16;
            ulonglong2 c0 = ((const ulonglong2*)S)[0];
            ulonglong2 c1 = ((const ulonglong2*)S)[1];
            ulonglong2 c2 = ((const ulonglong2*)S)[2];
            ulonglong2 c3 = ((const ulonglong2*)S)[3];
#pragma unroll
            for (int r = 0; r < 16; ++r) {
                ulonglong2 n0 = c0, n1 = c1, n2 = c2, n3 = c3;
                if (r < 15) {
                    const ulonglong2* Sn = (const ulonglong2*)(S + (r + 1) * WPAD);
                    n0 = Sn[0]; n1 = Sn[1]; n2 = Sn[2]; n3 = Sn[3];
                }
                if (doA) {
                    unsigned long long a0 = fma2(wA[0], c0.x, 0ull);
                    unsigned long long a1 = fma2(wA[1], c0.y, 0ull);
                    unsigned long long a2 = fma2(wA[2], c1.x, 0ull);
                    unsigned long long a3 = fma2(wA[3], c1.y, 0ull);
                    a0 = fma2(wA[4], c2.x, a0);
                    a1 = fma2(wA[5], c2.y, a1);
                    a2 = fma2(wA[6], c3.x, a2);
                    a3 = fma2(wA[7], c3.y, a3);
                    redA_[r * 33 + lane] = hsum2(add2(add2(a0, a1), add2(a2, a3)));
                }
                if (doC) {
                    unsigned long long a0 = fma2(wI[0], c0.x, 0ull);
                    unsigned long long a1 = fma2(wI[1], c0.y, 0ull);
                    unsigned long long a2 = fma2(wI[2], c1.x, 0ull);
                    unsigned long long a3 = fma2(wI[3], c1.y, 0ull);
                    a0 = fma2(wI[4], c2.x, a0);
                    a1 = fma2(wI[5], c2.y, a1);
                    a2 = fma2(wI[6], c3.x, a2);
                    a3 = fma2(wI[7], c3.y, a3);
                    redB_[r * 33 + lane] = hsum2(add2(add2(a0, a1), add2(a2, a3)));
                }
                c0 = n0; c1 = n1; c2 = n2; c3 = n3;
            }
        }
        POLL(2u * i + 1u);   // peers' h1_{i-2} (published 1 iter ago: max slack)
        __syncthreads();     // S1

        // ---- B: stage h1_{i-2} (LDGs fly under h0 finalize) ----
        float4 e0, e1;
        {
            const float* src = g_h1[i & 1] + (size_t)(b0 + srow) * Hsz;  // (i-2)&1 == i&1
            e0 = __ldcg((const float4*)(src + sc * 4));
            e1 = __ldcg((const float4*)(src + (sc + 32) * 4));
        }
        if (doA) {           // finalize h0_i (warp w -> row w), tree reduce
            float t[16];
#pragma unroll
            for (int q = 0; q < 16; ++q) t[q] = sRedA[q * 528 + warp * 33 + lane];
#pragma unroll
            for (int st = 1; st < 16; st <<= 1)
#pragma unroll
                for (int j = 0; j < 16; j += 2 * st) t[j] += t[j + st];
            __stcg(&g_h0[i & 1][(size_t)(b0 + warp) * Hsz + h0c + lane],
                   tanh_fast(p + t[0]));
        }
        {
            float* dst = sH1 + srow * WPAD;
            *(float4*)(dst + sc * 4)        = e0;
            *(float4*)(dst + (sc + 32) * 4) = e1;
        }
        __syncthreads();     // S2
        if (tid == 0) st_release(&g_flags[cta], 2u * i + 2u);   // publish h0_i

        // ---- C2: Whh1 partials on sH1 (u64 weights from sWH, row-prefetched) ----
        if (doC) {
            unsigned long long wH[8];
            const unsigned long long* wh64 = (const unsigned long long*)sWH;
#pragma unroll
            for (int j = 0; j < 8; ++j) wH[j] = wh64[(warp * 8 + j) * 32 + lane];
            float* red = sRedA + warp * 528;     // A tiles consumed at B: reuse
            const float* S = sH1 + warp * 16;
            ulonglong2 c0 = ((const ulonglong2*)S)[0];
            ulonglong2 c1 = ((const ulonglong2*)S)[1];
            ulonglong2 c2 = ((const ulonglong2*)S)[2];
            ulonglong2 c3 = ((const ulonglong2*)S)[3];
#pragma unroll
            for (int r = 0; r < 16; ++r) {
                ulonglong2 n0 = c0, n1 = c1, n2 = c2, n3 = c3;
                if (r < 15) {
                    const ulonglong2* Sn = (const ulonglong2*)(S + (r + 1) * WPAD);
                    n0 = Sn[0]; n1 = Sn[1]; n2 = Sn[2]; n3 = Sn[3];
                }
                unsigned long long a0 = fma2(wH[0], c0.x, 0ull);
                unsigned long long a1 = fma2(wH[1], c0.y, 0ull);
                unsigned long long a2 = fma2(wH[2], c1.x, 0ull);
                unsigned long long a3 = fma2(wH[3], c1.y, 0ull);
                a0 = fma2(wH[4], c2.x, a0);
                a1 = fma2(wH[5], c2.y, a1);
                a2 = fma2(wH[6], c3.x, a2);
                a3 = fma2(wH[7], c3.y, a3);
                red[r * 33 + lane] = hsum2(add2(add2(a0, a1), add2(a2, a3)));
                c0 = n0; c1 = n1; c2 = n2; c3 = n3;
            }
        }
        if (doA) POLL(2u * i + 2u);
        __syncthreads();     // S3

        // ---- D: finalize h1_{i-1} (tree reduce); stage h0_i (LDGs fly under it) ----
        if (doA) {
            const float* src = g_h0[i & 1] + (size_t)(b0 + srow) * Hsz;
            e0 = __ldcg((const float4*)(src + sc * 4));
            e1 = __ldcg((const float4*)(src + (sc + 32) * 4));
        }
        if (doC) {
            float t[16], u[16];
#pragma unroll
            for (int q = 0; q < 16; ++q) t[q] = sRedB[q * 528 + warp * 33 + lane];
#pragma unroll
            for (int q = 0; q < 16; ++q) u[q] = sRedA[q * 528 + warp * 33 + lane];
#pragma unroll
            for (int st = 1; st < 16; st <<= 1)
#pragma unroll
                for (int j = 0; j < 16; j += 2 * st) { t[j] += t[j + st]; u[j] += u[j + st]; }
            __stcg(&g_h1[(i - 1) & 1][(size_t)(b0 + warp) * Hsz + h0c + lane],
                   tanh_fast(bias1 + t[0] + u[0]));
        }
        if (doA) {
            float* dst = sH0 + srow * WPAD;
            *(float4*)(dst + sc * 4)        = e0;
            *(float4*)(dst + (sc + 32) * 4) = e1;
            if (i + 1 < Ssz)
                p = g_pre0p[((size_t)cta * Ssz + i + 1) * 512 + warp * 32 + lane];
        }
        __syncthreads();     // S4
        if (tid == 0) st_release(&g_flags[cta], 2u * i + 3u);   // publish h1_{i-1}
    }

    // ================= phase 3: head (16 CTAs, one per batch group) =================
    if ((cta & 7) == 0) {
        POLL(2u * Ssz + 3u);
        __syncthreads();
        if (warp < 8) {
            const float bo = bout[0];
#pragma unroll
            for (int rr = 0; rr < 2; ++rr) {
                const int b = b0 + warp * 2 + rr;
                const float* h = g_h1[(Ssz - 1) & 1] + (size_t)b * Hsz;
                float s = 0.0f;
#pragma unroll
                for (int j = 0; j < 8; ++j)
                    s += __ldcg(&h[lane + 32 * j]) * Wout[lane + 32 * j];
#pragma unroll
                for (int o = 16; o > 0; o >>= 1) s += __shfl_down_sync(0xFFFFFFFFu, s, o);
                if (lane == 0) out[b] = 1.0f / (1.0f + expf(-(s + bo)));
            }
        }
    }
#undef POLL
}

// ---------------- launch ----------------
extern "C" void kernel_launch(void* const* d_in, const int* in_sizes, int n_in,
                              void* d_out, int out_size) {
    const float* x    = (const float*)d_in[0];
    const float* Wih0 = (const float*)d_in[1];
    const float* Whh0 = (const float*)d_in[2];
    const float* bih0 = (const float*)d_in[3];
    const float* bhh0 = (const float*)d_in[4];
    const float* Wih1 = (const float*)d_in[5];
    const float* Whh1 = (const float*)d_in[6];
    const float* bih1 = (const float*)d_in[7];
    const float* bhh1 = (const float*)d_in[8];
    const float* Wout = (const float*)d_in[9];
    const float* bout = (const float*)d_in[10];
    float* out = (float*)d_out;

    // smem: 2*16*WPAD + 32*528 + 256*32 floats = 33408 floats = 133,632 B
    const int smem_bytes = (2 * 16 * WPAD + 32 * 528 + 256 * 32) * (int)sizeof(float);
    static int configured = 0;
    if (!configured) {
        cudaFuncSetAttribute(fused_kernel, cudaFuncAttributeMaxDynamicSharedMemorySize, smem_bytes);
        configured = 1;
    }

    init_kernel<<<(Bsz * Hsz + 511) / 512, 512>>>();
    fused_kernel<<<NCTA, NTHR, smem_bytes>>>(x, Wih0, Whh0, bih0, bhh0,
                                             Wih1, Whh1, bih1, bhh1,
                                             Wout, bout, out);
}